// round 3
// baseline (speedup 1.0000x reference)
#include <cuda_runtime.h>
#include <math.h>

// Problem dims
#define BB 64     // batch
#define TT 110    // timesteps
#define PP 64     // series
#define HH 256    // hidden
#define KK 16     // connections
#define LL 100    // nets seq length
#define BT 16     // batch tile per CTA
#define SB (BB/BT)

// Output layout (tuple concat, all f32):
//   pred   (P,B,L,1) : 409600  @ 0
//   logvar (B,H)     : 16384   @ 409600
//   mu     (B,H)     : 16384   @ 425984
//   mean   (B,P)     : 4096    @ 442368
//   disp   (B,P)     : 4096    @ 446464

__device__ float g_z[BB * HH];   // latent z scratch

__device__ __forceinline__ float sigmoidf_(float x) { return 1.0f / (1.0f + expf(-x)); }

// ------------------------------------------------------------------
// Encoder: gru_left (10 steps) -> gru_1 (1 step, h0=0) -> heads + z
// one CTA per batch element, thread t = hidden unit t
// ------------------------------------------------------------------
__global__ void __launch_bounds__(256) encoder_kernel(
    const float* __restrict__ X,
    const float* __restrict__ Wih_l, const float* __restrict__ Whh_l,
    const float* __restrict__ bih_l, const float* __restrict__ bhh_l,
    const float* __restrict__ Wih1,
    const float* __restrict__ bih1, const float* __restrict__ bhh1,
    const float* __restrict__ Wmu,  const float* __restrict__ bmu,
    const float* __restrict__ Wstd, const float* __restrict__ bstd,
    const float* __restrict__ Wmean,const float* __restrict__ bmean,
    const float* __restrict__ Wdisp,const float* __restrict__ bdisp,
    const float* __restrict__ z_noise,
    float* __restrict__ out_logvar, float* __restrict__ out_mu,
    float* __restrict__ out_mean,   float* __restrict__ out_disp)
{
    const int b = blockIdx.x;
    const int t = threadIdx.x;          // hidden unit 0..255
    __shared__ float hs[HH];
    __shared__ float xs[PP];
    hs[t] = 0.0f;
    __syncthreads();

    const float bir = bih_l[t]        + bhh_l[t];
    const float biz = bih_l[HH + t]   + bhh_l[HH + t];
    const float bin = bih_l[2*HH + t];
    const float bhn = bhh_l[2*HH + t];

    const float* wr = Wih_l + (size_t)t * PP;
    const float* wz = Wih_l + (size_t)(HH + t) * PP;
    const float* wn = Wih_l + (size_t)(2*HH + t) * PP;
    const float* ur = Whh_l + (size_t)t * HH;
    const float* uz = Whh_l + (size_t)(HH + t) * HH;
    const float* un = Whh_l + (size_t)(2*HH + t) * HH;

    for (int s = 0; s < 10; s++) {
        if (t < PP) xs[t] = X[((size_t)b * TT + s) * PP + t];
        __syncthreads();
        float ar = bir, az = biz, an = bin, gn = bhn;
        #pragma unroll 4
        for (int k = 0; k < PP; k += 4) {
            float4 w0 = *(const float4*)(wr + k);
            float4 w1 = *(const float4*)(wz + k);
            float4 w2 = *(const float4*)(wn + k);
            float4 xv = *(const float4*)(&xs[k]);
            ar += xv.x*w0.x + xv.y*w0.y + xv.z*w0.z + xv.w*w0.w;
            az += xv.x*w1.x + xv.y*w1.y + xv.z*w1.z + xv.w*w1.w;
            an += xv.x*w2.x + xv.y*w2.y + xv.z*w2.z + xv.w*w2.w;
        }
        #pragma unroll 4
        for (int k = 0; k < HH; k += 4) {
            float4 w0 = *(const float4*)(ur + k);
            float4 w1 = *(const float4*)(uz + k);
            float4 w2 = *(const float4*)(un + k);
            float4 hv = *(const float4*)(&hs[k]);
            ar += hv.x*w0.x + hv.y*w0.y + hv.z*w0.z + hv.w*w0.w;
            az += hv.x*w1.x + hv.y*w1.y + hv.z*w1.z + hv.w*w1.w;
            gn += hv.x*w2.x + hv.y*w2.y + hv.z*w2.z + hv.w*w2.w;
        }
        float r  = sigmoidf_(ar);
        float zg = sigmoidf_(az);
        float n  = tanhf(an + r * gn);
        float hold = hs[t];
        float hnew = (1.0f - zg) * n + zg * hold;
        __syncthreads();
        hs[t] = hnew;
        __syncthreads();
    }

    // gru_1: one step, hidden state = 0 -> gh is just b_hh_1
    {
        float ar = bih1[t]        + bhh1[t];
        float az = bih1[HH + t]   + bhh1[HH + t];
        float an = bih1[2*HH + t];
        float gn = bhh1[2*HH + t];
        const float* w0p = Wih1 + (size_t)t * HH;
        const float* w1p = Wih1 + (size_t)(HH + t) * HH;
        const float* w2p = Wih1 + (size_t)(2*HH + t) * HH;
        #pragma unroll 4
        for (int k = 0; k < HH; k += 4) {
            float4 w0 = *(const float4*)(w0p + k);
            float4 w1 = *(const float4*)(w1p + k);
            float4 w2 = *(const float4*)(w2p + k);
            float4 hv = *(const float4*)(&hs[k]);
            ar += hv.x*w0.x + hv.y*w0.y + hv.z*w0.z + hv.w*w0.w;
            az += hv.x*w1.x + hv.y*w1.y + hv.z*w1.z + hv.w*w1.w;
            an += hv.x*w2.x + hv.y*w2.y + hv.z*w2.z + hv.w*w2.w;
        }
        float r  = sigmoidf_(ar);
        float zg = sigmoidf_(az);
        float n  = tanhf(an + r * gn);
        float h1 = (1.0f - zg) * n;
        __syncthreads();
        hs[t] = h1;
        __syncthreads();
    }

    // heads
    {
        float mu = bmu[t], lv = bstd[t];
        const float* wm = Wmu  + (size_t)t * HH;
        const float* ws = Wstd + (size_t)t * HH;
        #pragma unroll 4
        for (int k = 0; k < HH; k += 4) {
            float4 w0 = *(const float4*)(wm + k);
            float4 w1 = *(const float4*)(ws + k);
            float4 hv = *(const float4*)(&hs[k]);
            mu += hv.x*w0.x + hv.y*w0.y + hv.z*w0.z + hv.w*w0.w;
            lv += hv.x*w1.x + hv.y*w1.y + hv.z*w1.z + hv.w*w1.w;
        }
        out_mu[b*HH + t]     = mu;
        out_logvar[b*HH + t] = lv;
        g_z[b*HH + t] = mu + expf(0.5f * lv) * z_noise[b*HH + t];

        if (t < PP) {
            float m = bmean[t], d = bdisp[t];
            const float* wme = Wmean + (size_t)t * HH;
            const float* wd  = Wdisp + (size_t)t * HH;
            #pragma unroll 4
            for (int k = 0; k < HH; k += 4) {
                float4 w0 = *(const float4*)(wme + k);
                float4 w1 = *(const float4*)(wd + k);
                float4 hv = *(const float4*)(&hs[k]);
                m += hv.x*w0.x + hv.y*w0.y + hv.z*w0.z + hv.w*w0.w;
                d += hv.x*w1.x + hv.y*w1.y + hv.z*w1.z + hv.w*w1.w;
            }
            m = expf(m);
            m = fminf(fmaxf(m, 1e-5f), 1e6f);
            d = log1pf(expf(d));
            d = fminf(fmaxf(d, 1e-4f), 1e4f);
            out_mean[b*PP + t] = m;
            out_disp[b*PP + t] = d;
        }
    }
}

// ------------------------------------------------------------------
// Per-series GRU nets: grid (P, B/BT), 256 threads (thread t = unit t)
// 100-step scan; h tile (BT x 256) in SMEM; weights streamed from L2
// row-sequentially per thread (L1-friendly). pred written every step.
// ------------------------------------------------------------------
__global__ void __launch_bounds__(256) nets_kernel(
    const float* __restrict__ X,
    const int*   __restrict__ conn_idx,
    const float* __restrict__ Wih,   // (P, 768, 16)
    const float* __restrict__ Whh,   // (P, 768, 256)
    const float* __restrict__ bih,   // (P, 768)
    const float* __restrict__ bhh,   // (P, 768)
    const float* __restrict__ Wlin,  // (P, 1, 256)
    const float* __restrict__ blin,  // (P, 1)
    float* __restrict__ pred)        // (P, B, L, 1)
{
    const int p  = blockIdx.x;
    const int b0 = blockIdx.y * BT;
    const int t  = threadIdx.x;      // hidden unit 0..255

    __shared__ float hs[BT][HH];
    __shared__ float xg[BT][KK];
    __shared__ float wlin_s[HH];
    __shared__ int   cidx[KK];

    if (t < KK) cidx[t] = conn_idx[p*KK + t];
    wlin_s[t] = Wlin[(size_t)p * HH + t];
    #pragma unroll
    for (int b = 0; b < BT; b++) hs[b][t] = g_z[(size_t)(b0 + b) * HH + t];

    const float blinv = blin[p];
    const size_t pb = (size_t)p * 768;
    const float brc  = bih[pb + t]        + bhh[pb + t];
    const float bzc  = bih[pb + HH + t]   + bhh[pb + HH + t];
    const float bin_ = bih[pb + 2*HH + t];
    const float bhn_ = bhh[pb + 2*HH + t];

    const float* wih_r = Wih + (pb + t)        * KK;
    const float* wih_z = Wih + (pb + HH + t)   * KK;
    const float* wih_n = Wih + (pb + 2*HH + t) * KK;
    const float* whh_r = Whh + (pb + t)        * HH;
    const float* whh_z = Whh + (pb + HH + t)   * HH;
    const float* whh_n = Whh + (pb + 2*HH + t) * HH;

    __syncthreads();

    for (int l = 0; l < LL; l++) {
        // gather inputs for this step: seq[l=0] = zero pad row; else X[:, 9+l, conn]
        {
            const int bb = t >> 4, kk = t & 15;   // 256 threads == 16*16
            xg[bb][kk] = (l == 0) ? 0.0f
                : X[((size_t)(b0 + bb) * TT + (9 + l)) * PP + cidx[kk]];
        }
        __syncthreads();

        float ar[BT], az[BT], gin[BT], ghn[BT];
        #pragma unroll
        for (int b = 0; b < BT; b++) { ar[b]=brc; az[b]=bzc; gin[b]=bin_; ghn[b]=bhn_; }

        // input contribution (K=16)
        #pragma unroll
        for (int k = 0; k < KK; k += 4) {
            float4 w0 = *(const float4*)(wih_r + k);
            float4 w1 = *(const float4*)(wih_z + k);
            float4 w2 = *(const float4*)(wih_n + k);
            #pragma unroll
            for (int b = 0; b < BT; b++) {
                float4 xv = *(const float4*)(&xg[b][k]);
                ar[b]  += xv.x*w0.x + xv.y*w0.y + xv.z*w0.z + xv.w*w0.w;
                az[b]  += xv.x*w1.x + xv.y*w1.y + xv.z*w1.z + xv.w*w1.w;
                gin[b] += xv.x*w2.x + xv.y*w2.y + xv.z*w2.z + xv.w*w2.w;
            }
        }

        // hidden contribution (H=256) — the hot loop
        #pragma unroll 2
        for (int k = 0; k < HH; k += 4) {
            float4 w0 = *(const float4*)(whh_r + k);
            float4 w1 = *(const float4*)(whh_z + k);
            float4 w2 = *(const float4*)(whh_n + k);
            #pragma unroll
            for (int b = 0; b < BT; b++) {
                float4 hv = *(const float4*)(&hs[b][k]);
                ar[b]  += hv.x*w0.x + hv.y*w0.y + hv.z*w0.z + hv.w*w0.w;
                az[b]  += hv.x*w1.x + hv.y*w1.y + hv.z*w1.z + hv.w*w1.w;
                ghn[b] += hv.x*w2.x + hv.y*w2.y + hv.z*w2.z + hv.w*w2.w;
            }
        }

        // gates -> new hidden (reuse ar[] for hnew)
        #pragma unroll
        for (int b = 0; b < BT; b++) {
            float r  = sigmoidf_(ar[b]);
            float zg = sigmoidf_(az[b]);
            float n  = tanhf(gin[b] + r * ghn[b]);
            float hold = hs[b][t];
            ar[b] = (1.0f - zg) * n + zg * hold;
        }
        __syncthreads();     // all reads of old h complete
        #pragma unroll
        for (int b = 0; b < BT; b++) hs[b][t] = ar[b];
        __syncthreads();     // new h visible

        // pred: relu(h) . Wlin + blin ; 8 warps x 2 batches each
        {
            const int w = t >> 5, lane = t & 31;
            #pragma unroll
            for (int bi = 0; bi < 2; bi++) {
                const int bb = w*2 + bi;
                float s = 0.0f;
                #pragma unroll
                for (int j = lane; j < HH; j += 32)
                    s += fmaxf(hs[bb][j], 0.0f) * wlin_s[j];
                #pragma unroll
                for (int o = 16; o > 0; o >>= 1)
                    s += __shfl_xor_sync(0xffffffffu, s, o);
                if (lane == 0)
                    pred[((size_t)(p*BB + b0 + bb)) * LL + l] = s + blinv;
            }
        }
        // next iteration's gather only touches xg (already consumed) and
        // is followed by a barrier, so no extra sync needed here
    }
}

extern "C" void kernel_launch(void* const* d_in, const int* in_sizes, int n_in,
                              void* d_out, int out_size)
{
    const float* X         = (const float*)d_in[0];
    const int*   conn_idx  = (const int*)  d_in[1];
    const float* W_ih_left = (const float*)d_in[2];
    const float* W_hh_left = (const float*)d_in[3];
    const float* b_ih_left = (const float*)d_in[4];
    const float* b_hh_left = (const float*)d_in[5];
    const float* W_ih_1    = (const float*)d_in[6];
    // d_in[7] = W_hh_1: unused (hidden state is 0 for gru_1's single step)
    const float* b_ih_1    = (const float*)d_in[8];
    const float* b_hh_1    = (const float*)d_in[9];
    const float* W_mu      = (const float*)d_in[10];
    const float* b_mu      = (const float*)d_in[11];
    const float* W_std     = (const float*)d_in[12];
    const float* b_std     = (const float*)d_in[13];
    const float* W_mean    = (const float*)d_in[14];
    const float* b_mean    = (const float*)d_in[15];
    const float* W_disp    = (const float*)d_in[16];
    const float* b_disp    = (const float*)d_in[17];
    const float* W_ih_nets = (const float*)d_in[18];
    const float* W_hh_nets = (const float*)d_in[19];
    const float* b_ih_nets = (const float*)d_in[20];
    const float* b_hh_nets = (const float*)d_in[21];
    const float* W_lin     = (const float*)d_in[22];
    const float* b_lin     = (const float*)d_in[23];
    const float* z_noise   = (const float*)d_in[24];

    float* out = (float*)d_out;
    float* pred       = out;                       // 409600
    float* out_logvar = out + 409600;              // 16384
    float* out_mu     = out + 409600 + 16384;      // 16384
    float* out_mean   = out + 409600 + 2*16384;    // 4096
    float* out_disp   = out + 409600 + 2*16384 + 4096;

    encoder_kernel<<<BB, 256>>>(
        X, W_ih_left, W_hh_left, b_ih_left, b_hh_left,
        W_ih_1, b_ih_1, b_hh_1,
        W_mu, b_mu, W_std, b_std, W_mean, b_mean, W_disp, b_disp,
        z_noise, out_logvar, out_mu, out_mean, out_disp);

    dim3 grid(PP, SB);
    nets_kernel<<<grid, 256>>>(
        X, conn_idx, W_ih_nets, W_hh_nets, b_ih_nets, b_hh_nets,
        W_lin, b_lin, pred);
}

// round 4
// speedup vs baseline: 1.6413x; 1.6413x over previous
#include <cuda_runtime.h>
#include <math.h>

// Problem dims
#define BB 64     // batch
#define TT 110    // timesteps
#define PP 64     // series
#define HH 256    // hidden
#define KK 16     // connections
#define LL 100    // nets seq length

typedef unsigned long long u64;

// Output layout (tuple concat, all f32):
//   pred   (P,B,L,1) : 409600  @ 0
//   logvar (B,H)     : 16384   @ 409600
//   mu     (B,H)     : 16384   @ 425984
//   mean   (B,P)     : 4096    @ 442368
//   disp   (B,P)     : 4096    @ 446464

__device__ float g_z[BB * HH];                       // latent z scratch
__device__ float g_WThh[(size_t)PP * HH * 768];      // 48MB: Whh_nets transposed [p][k][768]
__device__ float g_WTih[(size_t)PP * KK * 768];      // 3MB:  Wih_nets transposed [p][k][768]
__device__ float g_WTenc[606208];                    // encoder weights transposed

#define OFF_HHL  0        // W_hh_left^T  [256][768]
#define OFF_IHL  196608   // W_ih_left^T  [64][768]
#define OFF_IH1  245760   // W_ih_1^T     [256][768]
#define OFF_MU   442368   // W_mu^T       [256][256]
#define OFF_STD  507904   // W_std^T      [256][256]
#define OFF_MEAN 573440   // W_mean^T     [256][64]
#define OFF_DISP 589824   // W_disp^T     [256][64]

__device__ __forceinline__ u64 pk2(float x) {
    u64 r; asm("mov.b64 %0, {%1, %1};" : "=l"(r) : "f"(x)); return r;
}
__device__ __forceinline__ u64 ffma2(u64 a, u64 b, u64 c) {
    u64 d; asm("fma.rn.f32x2 %0, %1, %2, %3;" : "=l"(d) : "l"(a), "l"(b), "l"(c)); return d;
}
__device__ __forceinline__ void upk2(u64 a, float& lo, float& hi) {
    asm("mov.b64 {%0, %1}, %2;" : "=f"(lo), "=f"(hi) : "l"(a));
}
__device__ __forceinline__ float fsig(float x) {
    return __fdividef(1.0f, 1.0f + __expf(-x));
}
__device__ __forceinline__ float ftanh_(float x) {
    // tanh via exp; ~1e-6 rel err (tanh.approx would be ~5e-4 abs: too risky)
    float e = __expf(fminf(fmaxf(2.0f * x, -80.0f), 80.0f));
    return __fdividef(e - 1.0f, e + 1.0f);
}

// ------------------------------------------------------------------
// Batched tiled transpose: in (Z, R, C) -> out (Z, C, R)
// ------------------------------------------------------------------
__global__ void transpose_k(const float* __restrict__ in, float* __restrict__ out,
                            int R, int C)
{
    __shared__ float tile[32][33];
    const size_t zoff = (size_t)blockIdx.z * R * C;
    in  += zoff;
    out += zoff;
    const int x = blockIdx.x * 32 + threadIdx.x;   // input col
    const int ybase = blockIdx.y * 32;
    #pragma unroll
    for (int j = threadIdx.y; j < 32; j += 8) {
        int y = ybase + j;
        if (x < C && y < R) tile[j][threadIdx.x] = in[(size_t)y * C + x];
    }
    __syncthreads();
    const int xo = ybase + threadIdx.x;            // output col = input row
    const int yobase = blockIdx.x * 32;
    #pragma unroll
    for (int j = threadIdx.y; j < 32; j += 8) {
        int yo = yobase + j;                       // output row = input col
        if (yo < C && xo < R) out[(size_t)yo * R + xo] = tile[threadIdx.x][j];
    }
}

// ------------------------------------------------------------------
// Encoder: gru_left (10 steps) -> gru_1 (1 step, h0=0) -> heads + z
// one CTA per batch element, thread t = hidden unit t; coalesced weights
// ------------------------------------------------------------------
__global__ void __launch_bounds__(256) encoder_kernel(
    const float* __restrict__ X,
    const float* __restrict__ bih_l, const float* __restrict__ bhh_l,
    const float* __restrict__ bih1,  const float* __restrict__ bhh1,
    const float* __restrict__ bmu,   const float* __restrict__ bstd,
    const float* __restrict__ bmean, const float* __restrict__ bdisp,
    const float* __restrict__ z_noise,
    float* __restrict__ out_logvar, float* __restrict__ out_mu,
    float* __restrict__ out_mean,   float* __restrict__ out_disp)
{
    const int b = blockIdx.x;
    const int t = threadIdx.x;
    __shared__ float hs[HH];
    __shared__ float xs[PP];
    hs[t] = 0.0f;

    const float bir = bih_l[t]        + bhh_l[t];
    const float biz = bih_l[HH + t]   + bhh_l[HH + t];
    const float bin = bih_l[2*HH + t];
    const float bhn = bhh_l[2*HH + t];
    const float* __restrict__ Wh = g_WTenc + OFF_HHL;   // [k][768]
    const float* __restrict__ Wi = g_WTenc + OFF_IHL;   // [k][768]
    __syncthreads();

    for (int s = 0; s < 10; s++) {
        if (t < PP) xs[t] = X[((size_t)b * TT + s) * PP + t];
        __syncthreads();
        float ar = bir, az = biz, an = bin, gn = bhn;
        #pragma unroll 4
        for (int k = 0; k < HH; k++) {
            float hk = hs[k];
            ar += hk * Wh[k*768 + t];
            az += hk * Wh[k*768 + 256 + t];
            gn += hk * Wh[k*768 + 512 + t];
        }
        #pragma unroll 4
        for (int k = 0; k < PP; k++) {
            float xk = xs[k];
            ar += xk * Wi[k*768 + t];
            az += xk * Wi[k*768 + 256 + t];
            an += xk * Wi[k*768 + 512 + t];
        }
        float r  = fsig(ar);
        float zz = fsig(az);
        float n  = ftanh_(an + r * gn);
        float hnew = (1.0f - zz) * n + zz * hs[t];
        __syncthreads();
        hs[t] = hnew;
        __syncthreads();
    }

    // gru_1: one step, hidden state = 0 -> gh is just b_hh_1
    {
        const float* __restrict__ W1 = g_WTenc + OFF_IH1;
        float ar = bih1[t]        + bhh1[t];
        float az = bih1[HH + t]   + bhh1[HH + t];
        float an = bih1[2*HH + t];
        float gn = bhh1[2*HH + t];
        #pragma unroll 4
        for (int k = 0; k < HH; k++) {
            float hk = hs[k];
            ar += hk * W1[k*768 + t];
            az += hk * W1[k*768 + 256 + t];
            an += hk * W1[k*768 + 512 + t];
        }
        float r  = fsig(ar);
        float zz = fsig(az);
        float n  = ftanh_(an + r * gn);
        float h1 = (1.0f - zz) * n;
        __syncthreads();
        hs[t] = h1;
        __syncthreads();
    }

    // heads
    {
        float mu = bmu[t], lv = bstd[t];
        const float* __restrict__ Wm = g_WTenc + OFF_MU;
        const float* __restrict__ Ws = g_WTenc + OFF_STD;
        #pragma unroll 4
        for (int k = 0; k < HH; k++) {
            float hk = hs[k];
            mu += hk * Wm[k*256 + t];
            lv += hk * Ws[k*256 + t];
        }
        out_mu[b*HH + t]     = mu;
        out_logvar[b*HH + t] = lv;
        g_z[b*HH + t] = mu + expf(0.5f * lv) * z_noise[b*HH + t];

        if (t < PP) {
            float m = bmean[t], d = bdisp[t];
            const float* __restrict__ Wme = g_WTenc + OFF_MEAN;
            const float* __restrict__ Wd  = g_WTenc + OFF_DISP;
            #pragma unroll 4
            for (int k = 0; k < HH; k++) {
                float hk = hs[k];
                m += hk * Wme[k*64 + t];
                d += hk * Wd[k*64 + t];
            }
            m = expf(m);
            m = fminf(fmaxf(m, 1e-5f), 1e6f);
            d = log1pf(expf(d));
            d = fminf(fmaxf(d, 1e-4f), 1e4f);
            out_mean[b*PP + t] = m;
            out_disp[b*PP + t] = d;
        }
    }
}

// ------------------------------------------------------------------
// Per-series GRU nets: grid (64, 2), 512 threads = 2 groups x 256 units.
// Group g handles batches b0c+g*16 .. +15. h stored k-major (hs2[k][b],
// row stride 36) so LDS.128 yields two f32x2 operands directly.
// Accumulators packed over batch pairs -> fma.rn.f32x2 (2x FP32 rate).
// Weights pre-transposed -> coalesced LDG.32.
// ------------------------------------------------------------------
__global__ void __launch_bounds__(512, 1) nets_kernel(
    const float* __restrict__ X,
    const int*   __restrict__ conn_idx,
    const float* __restrict__ bih,   // (P, 768)
    const float* __restrict__ bhh,   // (P, 768)
    const float* __restrict__ Wlin,  // (P, 1, 256)
    const float* __restrict__ blin,  // (P, 1)
    float* __restrict__ pred)        // (P, B, L, 1)
{
    const int p    = blockIdx.x;
    const int b0c  = blockIdx.y * 32;
    const int tid  = threadIdx.x;
    const int g    = tid >> 8;        // batch-group 0/1
    const int t    = tid & 255;       // hidden unit
    const int g16  = g << 4;
    const int lane = tid & 31;
    const int wg   = (tid >> 5) & 7;  // warp within group

    __shared__ __align__(16) float hs2[HH * 36];   // [k][b], stride 36 (pad)
    __shared__ __align__(16) float xg2[KK * 36];   // [k][b]
    __shared__ float psum[2][8][16];
    __shared__ int   cidx[KK];

    if (tid < KK) cidx[tid] = conn_idx[p*KK + tid];
    for (int i = tid; i < KK*36; i += 512) xg2[i] = 0.0f;   // step 0 = zero pad row
    #pragma unroll
    for (int j = 0; j < 16; j++)
        hs2[t*36 + g16 + j] = g_z[(size_t)(b0c + g16 + j) * HH + t];

    const size_t pb = (size_t)p * 768;
    const u64 brc2 = pk2(bih[pb + t]       + bhh[pb + t]);
    const u64 bzc2 = pk2(bih[pb + 256 + t] + bhh[pb + 256 + t]);
    const u64 bin2 = pk2(bih[pb + 512 + t]);
    const u64 bhn2 = pk2(bhh[pb + 512 + t]);
    const float wl  = Wlin[(size_t)p * HH + t];
    const float blv = blin[p];
    const float* __restrict__ Wh = g_WThh + (size_t)p * HH * 768;  // [k][768]
    const float* __restrict__ Wi = g_WTih + (size_t)p * KK * 768;  // [k][768]

    __syncthreads();

    for (int l = 0; l < LL; l++) {
        u64 ar2[8], az2[8], gi2[8], gh2[8];
        #pragma unroll
        for (int q = 0; q < 8; q++) { ar2[q]=brc2; az2[q]=bzc2; gi2[q]=bin2; gh2[q]=bhn2; }

        // input contribution (K = 16)
        #pragma unroll
        for (int k = 0; k < KK; k += 4) {
            #pragma unroll
            for (int j = 0; j < 4; j++) {
                const float* r_ = Wi + (size_t)(k + j) * 768;
                const u64 wr = pk2(r_[t]);
                const u64 wz = pk2(r_[256 + t]);
                const u64 wn = pk2(r_[512 + t]);
                const ulonglong2* hp =
                    reinterpret_cast<const ulonglong2*>(&xg2[(k + j)*36 + g16]);
                #pragma unroll
                for (int q = 0; q < 4; q++) {
                    ulonglong2 hv = hp[q];
                    ar2[2*q]   = ffma2(hv.x, wr, ar2[2*q]);
                    az2[2*q]   = ffma2(hv.x, wz, az2[2*q]);
                    gi2[2*q]   = ffma2(hv.x, wn, gi2[2*q]);
                    ar2[2*q+1] = ffma2(hv.y, wr, ar2[2*q+1]);
                    az2[2*q+1] = ffma2(hv.y, wz, az2[2*q+1]);
                    gi2[2*q+1] = ffma2(hv.y, wn, gi2[2*q+1]);
                }
            }
        }

        // hidden contribution (H = 256) — the hot loop
        #pragma unroll 1
        for (int k = 0; k < HH; k += 4) {
            #pragma unroll
            for (int j = 0; j < 4; j++) {
                const float* r_ = Wh + (size_t)(k + j) * 768;
                const u64 wr = pk2(r_[t]);
                const u64 wz = pk2(r_[256 + t]);
                const u64 wn = pk2(r_[512 + t]);
                const ulonglong2* hp =
                    reinterpret_cast<const ulonglong2*>(&hs2[(k + j)*36 + g16]);
                #pragma unroll
                for (int q = 0; q < 4; q++) {
                    ulonglong2 hv = hp[q];
                    ar2[2*q]   = ffma2(hv.x, wr, ar2[2*q]);
                    az2[2*q]   = ffma2(hv.x, wz, az2[2*q]);
                    gh2[2*q]   = ffma2(hv.x, wn, gh2[2*q]);
                    ar2[2*q+1] = ffma2(hv.y, wr, ar2[2*q+1]);
                    az2[2*q+1] = ffma2(hv.y, wz, az2[2*q+1]);
                    gh2[2*q+1] = ffma2(hv.y, wn, gh2[2*q+1]);
                }
            }
        }

        // old h for the z-gate mix (read pre-barrier)
        float hold[16];
        #pragma unroll
        for (int j = 0; j < 4; j++) {
            float4 hv = *reinterpret_cast<const float4*>(&hs2[t*36 + g16 + 4*j]);
            hold[4*j]   = hv.x; hold[4*j+1] = hv.y;
            hold[4*j+2] = hv.z; hold[4*j+3] = hv.w;
        }

        float hnew[16];
        #pragma unroll
        for (int q = 0; q < 8; q++) {
            float a0,a1,z0,z1,i0,i1,n0,n1;
            upk2(ar2[q], a0, a1);
            upk2(az2[q], z0, z1);
            upk2(gi2[q], i0, i1);
            upk2(gh2[q], n0, n1);
            float r0 = fsig(a0), r1 = fsig(a1);
            float zz0 = fsig(z0), zz1 = fsig(z1);
            float nn0 = ftanh_(i0 + r0 * n0);
            float nn1 = ftanh_(i1 + r1 * n1);
            hnew[2*q]   = (1.0f - zz0) * nn0 + zz0 * hold[2*q];
            hnew[2*q+1] = (1.0f - zz1) * nn1 + zz1 * hold[2*q+1];
        }

        // pred partials from registers: warp-reduce per batch
        #pragma unroll
        for (int i = 0; i < 16; i++) {
            float v = fmaxf(hnew[i], 0.0f) * wl;
            v += __shfl_xor_sync(0xffffffffu, v, 16);
            v += __shfl_xor_sync(0xffffffffu, v, 8);
            v += __shfl_xor_sync(0xffffffffu, v, 4);
            v += __shfl_xor_sync(0xffffffffu, v, 2);
            v += __shfl_xor_sync(0xffffffffu, v, 1);
            if (lane == i) psum[g][wg][i] = v;
        }

        __syncthreads();   // all reads of old hs2/xg2 + psum writes complete

        // commit new hidden state (k-major)
        #pragma unroll
        for (int j = 0; j < 4; j++) {
            *reinterpret_cast<float4*>(&hs2[t*36 + g16 + 4*j]) =
                make_float4(hnew[4*j], hnew[4*j+1], hnew[4*j+2], hnew[4*j+3]);
        }
        // gather inputs for step l+1: seq[l+1] = X[:, 10+l, conn]
        if (l < LL - 1) {
            int bb = tid >> 4, kk = tid & 15;
            xg2[kk*36 + bb] = X[((size_t)(b0c + bb) * TT + (10 + l)) * PP + cidx[kk]];
        }
        // finalize pred for step l (psum visible post-barrier)
        if (tid < 32) {
            int gg = tid >> 4, bidx = tid & 15;
            float s = 0.0f;
            #pragma unroll
            for (int w = 0; w < 8; w++) s += psum[gg][w][bidx];
            pred[((size_t)(p*BB + b0c + gg*16 + bidx)) * LL + l] = s + blv;
        }
        __syncthreads();   // hs2/xg2 writes + finalize visible before next compute
    }
}

extern "C" void kernel_launch(void* const* d_in, const int* in_sizes, int n_in,
                              void* d_out, int out_size)
{
    const float* X         = (const float*)d_in[0];
    const int*   conn_idx  = (const int*)  d_in[1];
    const float* W_ih_left = (const float*)d_in[2];
    const float* W_hh_left = (const float*)d_in[3];
    const float* b_ih_left = (const float*)d_in[4];
    const float* b_hh_left = (const float*)d_in[5];
    const float* W_ih_1    = (const float*)d_in[6];
    // d_in[7] = W_hh_1: unused (hidden state is 0 for gru_1's single step)
    const float* b_ih_1    = (const float*)d_in[8];
    const float* b_hh_1    = (const float*)d_in[9];
    const float* W_mu      = (const float*)d_in[10];
    const float* b_mu      = (const float*)d_in[11];
    const float* W_std     = (const float*)d_in[12];
    const float* b_std     = (const float*)d_in[13];
    const float* W_mean    = (const float*)d_in[14];
    const float* b_mean    = (const float*)d_in[15];
    const float* W_disp    = (const float*)d_in[16];
    const float* b_disp    = (const float*)d_in[17];
    const float* W_ih_nets = (const float*)d_in[18];
    const float* W_hh_nets = (const float*)d_in[19];
    const float* b_ih_nets = (const float*)d_in[20];
    const float* b_hh_nets = (const float*)d_in[21];
    const float* W_lin     = (const float*)d_in[22];
    const float* b_lin     = (const float*)d_in[23];
    const float* z_noise   = (const float*)d_in[24];

    float* out = (float*)d_out;
    float* pred       = out;
    float* out_logvar = out + 409600;
    float* out_mu     = out + 409600 + 16384;
    float* out_mean   = out + 409600 + 2*16384;
    float* out_disp   = out + 409600 + 2*16384 + 4096;

    float *wthh, *wtih, *wtenc;
    cudaGetSymbolAddress((void**)&wthh,  g_WThh);
    cudaGetSymbolAddress((void**)&wtih,  g_WTih);
    cudaGetSymbolAddress((void**)&wtenc, g_WTenc);

    dim3 tb(32, 8);
    // nets weights: per-p (768 x 256) -> [p][256][768], (768 x 16) -> [p][16][768]
    transpose_k<<<dim3(8, 24, PP), tb>>>(W_hh_nets, wthh, 768, 256);
    transpose_k<<<dim3(1, 24, PP), tb>>>(W_ih_nets, wtih, 768, 16);
    // encoder weights
    transpose_k<<<dim3(8, 24, 1), tb>>>(W_hh_left, wtenc + OFF_HHL, 768, 256);
    transpose_k<<<dim3(2, 24, 1), tb>>>(W_ih_left, wtenc + OFF_IHL, 768, 64);
    transpose_k<<<dim3(8, 24, 1), tb>>>(W_ih_1,    wtenc + OFF_IH1, 768, 256);
    transpose_k<<<dim3(8, 8, 1),  tb>>>(W_mu,      wtenc + OFF_MU,  256, 256);
    transpose_k<<<dim3(8, 8, 1),  tb>>>(W_std,     wtenc + OFF_STD, 256, 256);
    transpose_k<<<dim3(8, 2, 1),  tb>>>(W_mean,    wtenc + OFF_MEAN, 64, 256);
    transpose_k<<<dim3(8, 2, 1),  tb>>>(W_disp,    wtenc + OFF_DISP, 64, 256);

    encoder_kernel<<<BB, 256>>>(
        X, b_ih_left, b_hh_left, b_ih_1, b_hh_1,
        b_mu, b_std, b_mean, b_disp, z_noise,
        out_logvar, out_mu, out_mean, out_disp);

    nets_kernel<<<dim3(PP, BB/32), 512>>>(
        X, conn_idx, b_ih_nets, b_hh_nets, W_lin, b_lin, pred);
}